// round 11
// baseline (speedup 1.0000x reference)
#include <cuda_runtime.h>
#include <cuda_bf16.h>

// B=2, L=256, D=256. One fused kernel, 128 blocks x 1024 threads.
// X staged in 4 tiles of 64 k, double-buffered via cp.async.
// Buffers: Xs[2][256][66] floats (135168 B) + shWk[128][8] float2 (8192 B).
#define XS_STRIDE 66
#define XS_TILE_BYTES (256 * XS_STRIDE * 4)      // 67584
#define W_OFF  (2 * XS_TILE_BYTES)               // 135168
#define SMEM_DYN (W_OFF + 8192)                  // 143360

__device__ __forceinline__ float2 cmul(float2 a, float2 b) {
    return make_float2(a.x * b.x - a.y * b.y, a.x * b.y + a.y * b.x);
}
__device__ __forceinline__ float2 cadd(float2 a, float2 b) {
    return make_float2(a.x + b.x, a.y + b.y);
}
#define FMA2(acc, x, w) \
    asm("fma.rn.f32x2 %0, %1, %2, %0;" : "+l"(acc) : "l"(x), "l"(w))
#define ADD2(acc, y) \
    asm("add.rn.f32x2 %0, %0, %1;" : "+l"(acc) : "l"(y))
#define CP_ASYNC8(dst_u32, src_ptr) \
    asm volatile("cp.async.ca.shared.global [%0], [%1], 8;" \
                 :: "r"(dst_u32), "l"(src_ptr))
#define CP_COMMIT() asm volatile("cp.async.commit_group;")
#define CP_WAIT1()  asm volatile("cp.async.wait_group 1;")
#define CP_WAIT0()  asm volatile("cp.async.wait_group 0;")

__global__ __launch_bounds__(1024, 1)
void sioconv_fused(const float* __restrict__ X, const float* __restrict__ W,
                   const float* __restrict__ h0r, const float* __restrict__ h0i,
                   float* __restrict__ out) {
    extern __shared__ __align__(16) char smem[];
    float*  Xs   = (float*)smem;                  // [2][256][66]
    float2* shWk = (float2*)(smem + W_OFF);       // [128 k2][8 n]

    const int b  = blockIdx.x >> 6;
    const int dg = blockIdx.x & 63;
    const int n0 = dg * 8;
    const int t  = threadIdx.x;       // 0..1023
    const int lt = t & 255;           // l row
    const int kh = t >> 8;            // 0..3 k-quarter within each tile

    const float* Xb = X + b * 65536;
    const unsigned smem_base = (unsigned)__cvta_generic_to_shared(smem);

    // ---- cp.async stage W: 1024 float2 entries, 1 per thread (group 0)
    {
        int n = t >> 7, k2 = t & 127;
        CP_ASYNC8(smem_base + W_OFF + (unsigned)(k2 * 8 + n) * 8,
                  W + (n0 + n) * 256 + 2 * k2);
    }
    // ---- cp.async tile 0 into buf 0 (also group 0): 8 x 8B per thread
    const int sl = t >> 5;           // staging row (0..31 rows per i? no: e>>5)
#pragma unroll
    for (int i = 0; i < 8; i++) {
        int e = t + 1024 * i;        // 0..8191
        int l = e >> 5, c = e & 31;  // row l, 8B-chunk c (k = 2c)
        CP_ASYNC8(smem_base + (unsigned)(l * XS_STRIDE + 2 * c) * 4,
                  Xb + l * 256 + 0 * 64 + 2 * c);
    }
    CP_COMMIT();
    // ---- cp.async tile 1 into buf 1 (group 1)
#pragma unroll
    for (int i = 0; i < 8; i++) {
        int e = t + 1024 * i;
        int l = e >> 5, c = e & 31;
        CP_ASYNC8(smem_base + (unsigned)XS_TILE_BYTES +
                      (unsigned)(l * XS_STRIDE + 2 * c) * 4,
                  Xb + l * 256 + 1 * 64 + 2 * c);
    }
    CP_COMMIT();
    (void)sl;

    unsigned long long acc[8] = {0ull,0ull,0ull,0ull,0ull,0ull,0ull,0ull};

#pragma unroll
    for (int tile = 0; tile < 4; tile++) {
        if (tile < 2) { CP_WAIT1(); } else { CP_WAIT0(); }
        __syncthreads();             // tile's data visible to all

        const float*  xr = Xs + (tile & 1) * (256 * XS_STRIDE)
                              + lt * XS_STRIDE + kh * 16;
        const float2* wr = shWk + (tile * 32 + kh * 8) * 8;
#pragma unroll
        for (int j = 0; j < 8; j++) {
            unsigned long long x2 = *(const unsigned long long*)(xr + 2 * j);
            const ulonglong2* wp = (const ulonglong2*)(wr + j * 8);
            ulonglong2 w01 = wp[0], w23 = wp[1], w45 = wp[2], w67 = wp[3];
            FMA2(acc[0], x2, w01.x); FMA2(acc[1], x2, w01.y);
            FMA2(acc[2], x2, w23.x); FMA2(acc[3], x2, w23.y);
            FMA2(acc[4], x2, w45.x); FMA2(acc[5], x2, w45.y);
            FMA2(acc[6], x2, w67.x); FMA2(acc[7], x2, w67.y);
        }
        __syncthreads();             // all reads of this buffer done
        if (tile < 2) {
            // refill this buffer with tile+2
            const int nt = tile + 2;
            unsigned dbase = smem_base + (unsigned)((tile & 1) * XS_TILE_BYTES);
#pragma unroll
            for (int i = 0; i < 8; i++) {
                int e = t + 1024 * i;
                int l = e >> 5, c = e & 31;
                CP_ASYNC8(dbase + (unsigned)(l * XS_STRIDE + 2 * c) * 4,
                          Xb + l * 256 + nt * 64 + 2 * c);
            }
            CP_COMMIT();
        }
    }
    __syncthreads();   // safe to alias smem

    // ---- phase-2 smem layout (aliases Xs region; W region untouched but done)
    unsigned long long* scratch = (unsigned long long*)smem;  // [3][256][8]
    float2* sA   = (float2*)(smem + 49152);   // [4][256]
    float*  xsr  = (float*)(smem + 57344);    // [4][256]
    float2* wagA = (float2*)(smem + 61440);   // [4][8]
    float2* wagY = (float2*)(smem + 61696);   // [4][8]
    float2* preY = (float2*)(smem + 61952);   // [4][8]

    // ---- combine the 4 k-quarters
    if (kh != 0) {
#pragma unroll
        for (int n = 0; n < 8; n++)
            scratch[((kh - 1) * 256 + lt) * 8 + n] = acc[n];
    }
    __syncthreads();
    if (kh == 0) {
#pragma unroll
        for (int p = 0; p < 4; p++) {
            unsigned long long aRe = acc[2 * p], aIm = acc[2 * p + 1];
#pragma unroll
            for (int q = 0; q < 3; q++) {
                ADD2(aRe, scratch[(q * 256 + lt) * 8 + 2 * p]);
                ADD2(aIm, scratch[(q * 256 + lt) * 8 + 2 * p + 1]);
            }
            float r0, r1, i0, i1;
            asm("mov.b64 {%0, %1}, %2;" : "=f"(r0), "=f"(r1) : "l"(aRe));
            asm("mov.b64 {%0, %1}, %2;" : "=f"(i0), "=f"(i1) : "l"(aIm));
            float re = r0 + r1;
            float im = i0 + i1;
            float mag2 = re * re + im * im;
            float s = rsqrtf(mag2) * expf(-mag2);
            sA[p * 256 + lt] = make_float2(re * s, im * s);
        }
    }
    // ---- stage xhat real parts: xsr[j][l], 1024 entries, 1 per thread
    {
        int l = t >> 2;
        int j = t & 3;
        int d = dg * 4 + j;
        xsr[j * 256 + l] = (l == 0) ? h0r[d] : Xb[(l - 1) * 256 + d];
    }
    __syncthreads();

    // ---- reverse complex scan: group g = t>>8 handles series j = g
    const int g = t >> 8;
    const int tl = t & 255;       // reversed index
    const int l = 255 - tl;
    const int lane = t & 31;
    const int w = tl >> 5;

    float2 A, Y;
    {
        float2 a = sA[g * 256 + l];
        float2 xh;
        xh.x = xsr[g * 256 + l];
        xh.y = (l == 0) ? h0i[dg * 4 + g] : 0.f;
        A = a;
        Y = cmul(a, xh);
    }

    const unsigned mask = 0xffffffffu;
#pragma unroll
    for (int o = 1; o < 32; o <<= 1) {
        float2 pA, pY;
        pA.x = __shfl_up_sync(mask, A.x, o);
        pA.y = __shfl_up_sync(mask, A.y, o);
        pY.x = __shfl_up_sync(mask, Y.x, o);
        pY.y = __shfl_up_sync(mask, Y.y, o);
        if (lane >= o) {
            float2 nY = cadd(Y, cmul(A, pY));
            float2 nA = cmul(A, pA);
            Y = nY;
            A = nA;
        }
    }

    if (lane == 31) {
        wagA[g * 8 + w] = A;
        wagY[g * 8 + w] = Y;
    }
    __syncthreads();
    if (tl == 0) {
        float2 pY = make_float2(0.f, 0.f);
#pragma unroll
        for (int w2 = 0; w2 < 8; w2++) {
            preY[g * 8 + w2] = pY;
            pY = cadd(wagY[g * 8 + w2], cmul(wagA[g * 8 + w2], pY));
        }
    }
    __syncthreads();

    {
        float2 Yf = Y;
        if (w > 0) Yf = cadd(Yf, cmul(A, preY[g * 8 + w]));
        float r = Yf.x;
        if (l >= 1)   r += xsr[g * 256 + (l - 1)];
        if (l == 255) r += Xb[255 * 256 + dg * 4 + g];
        out[(b * 256 + l) * 256 + dg * 4 + g] = r;
    }
}

extern "C" void kernel_launch(void* const* d_in, const int* in_sizes, int n_in,
                              void* d_out, int out_size) {
    const float* x   = (const float*)d_in[0];
    const float* W   = (const float*)d_in[1];
    const float* h0r = (const float*)d_in[2];
    const float* h0i = (const float*)d_in[3];
    float* out = (float*)d_out;

    cudaFuncSetAttribute(sioconv_fused,
                         cudaFuncAttributeMaxDynamicSharedMemorySize, SMEM_DYN);
    sioconv_fused<<<128, 1024, SMEM_DYN>>>(x, W, h0r, h0i, out);
}